// round 1
// baseline (speedup 1.0000x reference)
#include <cuda_runtime.h>
#include <math.h>

// Problem constants (fixed by the reference)
#define VGRID   100
#define NBATCH  8
#define NPTS    65536
#define NPOINTS (NBATCH * NPTS)            // 524288
#define NVOX    (NBATCH * VGRID * VGRID * VGRID)  // 8,000,000 output voxels
#define CACC    7                          // x,y,z,f0,f1,f2,count
#define COUT    10

// 224 MB accumulator scratch: AoS, 7 floats per voxel.
// Static __device__ global (allowed; no runtime allocation).
__device__ __align__(16) float g_acc[(size_t)NVOX * CACC];

// ---------------------------------------------------------------------------
// Kernel 1: zero the accumulator (float4 vectorized, fully coalesced).
// NVOX*CACC = 56,000,000 floats = 14,000,000 float4 (exact).
// ---------------------------------------------------------------------------
__global__ void zero_acc_kernel() {
    const int n4 = NVOX * CACC / 4;  // 14,000,000
    int i = blockIdx.x * blockDim.x + threadIdx.x;
    float4* p = reinterpret_cast<float4*>(g_acc);
    if (i < n4) p[i] = make_float4(0.f, 0.f, 0.f, 0.f);
}

// ---------------------------------------------------------------------------
// Kernel 2: scatter points into the accumulator with atomics.
//
// Reference binning in fp32 semantics:
//   res   = float32(1.0 / float32(100 + 1e-12)) = 1.0f/100.0f
//   denom = res + 1e-12  -> rounds to res in fp32 (ulp(0.01) ~ 9.3e-10)
//   idx   = floor((c + res) / res), clipped to [0, 101]
// Bins 0 and 101 are the boundary shell that the reference slices away,
// so any point with idx outside [1,100] in any dim is simply skipped.
// ---------------------------------------------------------------------------
__global__ void scatter_kernel(const float* __restrict__ coords,
                               const float* __restrict__ feats) {
    int p = blockIdx.x * blockDim.x + threadIdx.x;
    if (p >= NPOINTS) return;

    const float RES = 1.0f / 100.0f;  // 0x3C23D70A, matches reference fp32

    float x = coords[3 * p + 0];
    float y = coords[3 * p + 1];
    float z = coords[3 * p + 2];

    int ix = (int)floorf((x + RES) / RES);
    int iy = (int)floorf((y + RES) / RES);
    int iz = (int)floorf((z + RES) / RES);

    // Keep only interior bins [1, 100]; shell is discarded by the reference.
    if (ix < 1 || ix > VGRID || iy < 1 || iy > VGRID || iz < 1 || iz > VGRID)
        return;

    float f0 = feats[3 * p + 0];
    float f1 = feats[3 * p + 1];
    float f2 = feats[3 * p + 2];

    int b = p / NPTS;  // NPTS = 65536, compiles to a shift
    int v = (((b * VGRID + (ix - 1)) * VGRID + (iy - 1)) * VGRID + (iz - 1));

    float* a = g_acc + (size_t)v * CACC;
    atomicAdd(a + 0, x);
    atomicAdd(a + 1, y);
    atomicAdd(a + 2, z);
    atomicAdd(a + 3, f0);
    atomicAdd(a + 4, f1);
    atomicAdd(a + 5, f2);
    atomicAdd(a + 6, 1.0f);
}

// ---------------------------------------------------------------------------
// Kernel 3: finalize. One thread per output voxel.
// Reads 28B/voxel from the accumulator (warp reads 896B contiguous),
// writes 40B/voxel to d_out (warp writes 1280B contiguous).
// Output channels: mean(x,y,z,f0,f1,f2), i/100, j/100, k/100, occupied.
// ---------------------------------------------------------------------------
__global__ void finalize_kernel(float* __restrict__ out) {
    int v = blockIdx.x * blockDim.x + threadIdx.x;
    if (v >= NVOX) return;

    const float* __restrict__ a = g_acc + (size_t)v * CACC;
    float s0 = a[0], s1 = a[1], s2 = a[2];
    float s3 = a[3], s4 = a[4], s5 = a[5];
    float cnt = a[6];

    float den = fmaxf(cnt, 1.0f);
    float inv = 1.0f / den;  // fp32 div; within tolerance of reference's /

    // v = ((b*100 + i)*100 + j)*100 + k
    int k = v % VGRID;
    int t = v / VGRID;
    int j = t % VGRID;
    t /= VGRID;
    int i = t % VGRID;

    float* __restrict__ o = out + (size_t)v * COUT;
    o[0] = s0 * inv;
    o[1] = s1 * inv;
    o[2] = s2 * inv;
    o[3] = s3 * inv;
    o[4] = s4 * inv;
    o[5] = s5 * inv;
    o[6] = (float)i / 100.0f;
    o[7] = (float)j / 100.0f;
    o[8] = (float)k / 100.0f;
    o[9] = (cnt > 0.0f) ? 1.0f : 0.0f;
}

// ---------------------------------------------------------------------------
// Launch: zero -> scatter -> finalize on the capture stream (default).
// ---------------------------------------------------------------------------
extern "C" void kernel_launch(void* const* d_in, const int* in_sizes, int n_in,
                              void* d_out, int out_size) {
    const float* coords = (const float*)d_in[0];
    const float* feats  = (const float*)d_in[1];
    float* out = (float*)d_out;

    {
        const int n4 = NVOX * CACC / 4;
        int threads = 256;
        int blocks = (n4 + threads - 1) / threads;
        zero_acc_kernel<<<blocks, threads>>>();
    }
    {
        int threads = 256;
        int blocks = (NPOINTS + threads - 1) / threads;
        scatter_kernel<<<blocks, threads>>>(coords, feats);
    }
    {
        int threads = 256;
        int blocks = (NVOX + threads - 1) / threads;
        finalize_kernel<<<blocks, threads>>>(out);
    }
}

// round 2
// speedup vs baseline: 3.1128x; 3.1128x over previous
#include <cuda_runtime.h>
#include <math.h>
#include <stdint.h>

// Problem constants (fixed by the reference)
#define VGRID   100
#define NBATCH  8
#define NPTS    65536
#define NPOINTS (NBATCH * NPTS)                   // 524288
#define NVOX    (NBATCH * VGRID * VGRID * VGRID)  // 8,000,000
#define COUT    10
#define NWORDS  (NVOX / 32)                       // 250,000 bitmap words

// 32B-padded accumulator record per voxel: [x,y,z,f0][f1,f2,cnt,pad]
// 256 MB static scratch, zero-initialized at module load and kept zero by
// the self-cleaning finalize kernel (graph-replay safe).
__device__ __align__(32) float4 g_acc[(size_t)NVOX * 2];
__device__ uint32_t g_bits[NWORDS];   // occupancy bitmap, self-cleaned too

// ---------------------------------------------------------------------------
// Scatter: one thread per point. Binning identical to round 1 (verified):
//   idx = floor((c + RES)/RES), keep interior bins [1,100].
// 3 atomics per point: 2x red.global.add.v4.f32 + 1 bitmap atomicOr.
// ---------------------------------------------------------------------------
__global__ void scatter_kernel(const float* __restrict__ coords,
                               const float* __restrict__ feats) {
    int p = blockIdx.x * blockDim.x + threadIdx.x;
    if (p >= NPOINTS) return;

    const float RES = 1.0f / 100.0f;

    float x = coords[3 * p + 0];
    float y = coords[3 * p + 1];
    float z = coords[3 * p + 2];

    int ix = (int)floorf((x + RES) / RES);
    int iy = (int)floorf((y + RES) / RES);
    int iz = (int)floorf((z + RES) / RES);

    if (ix < 1 || ix > VGRID || iy < 1 || iy > VGRID || iz < 1 || iz > VGRID)
        return;

    float f0 = feats[3 * p + 0];
    float f1 = feats[3 * p + 1];
    float f2 = feats[3 * p + 2];

    int b = p >> 16;  // p / NPTS
    int v = (((b * VGRID + (ix - 1)) * VGRID + (iy - 1)) * VGRID + (iz - 1));

    float4* rec = g_acc + (size_t)v * 2;

    asm volatile("red.global.add.v4.f32 [%0], {%1, %2, %3, %4};"
                 :: "l"(rec), "f"(x), "f"(y), "f"(z), "f"(f0) : "memory");
    asm volatile("red.global.add.v4.f32 [%0], {%1, %2, %3, %4};"
                 :: "l"(rec + 1), "f"(f1), "f"(f2), "f"(1.0f), "f"(0.0f)
                 : "memory");

    atomicOr(&g_bits[v >> 5], 1u << (v & 31));
}

// ---------------------------------------------------------------------------
// Finalize: one thread per voxel, 256 threads/block, 31250 blocks (exact).
//  - read bitmap word (one 4B word per warp, broadcast load)
//  - occupied: read 32B record, compute means, zero the record back
//  - lane 0 of each warp clears the bitmap word (if nonzero)
//  - stage 10 outputs/voxel in smem, write block's 10240B with STG.128
// ---------------------------------------------------------------------------
__global__ void finalize_kernel(float* __restrict__ out) {
    __shared__ float sh[256 * COUT];

    int v = blockIdx.x * 256 + threadIdx.x;

    uint32_t word = g_bits[v >> 5];
    bool occ = (word >> (v & 31)) & 1u;

    float m0 = 0.f, m1 = 0.f, m2 = 0.f, m3 = 0.f, m4 = 0.f, m5 = 0.f;
    if (occ) {
        float4* rec = g_acc + (size_t)v * 2;
        float4 a = rec[0];
        float4 b = rec[1];
        float inv = 1.0f / fmaxf(b.z, 1.0f);   // b.z = count (>0 here)
        m0 = a.x * inv; m1 = a.y * inv; m2 = a.z * inv;
        m3 = a.w * inv; m4 = b.x * inv; m5 = b.y * inv;
        // self-clean for the next graph replay
        float4 zero = make_float4(0.f, 0.f, 0.f, 0.f);
        rec[0] = zero;
        rec[1] = zero;
    }
    if ((v & 31) == 0 && word != 0u)
        g_bits[v >> 5] = 0u;

    // voxel coordinates: v = ((b*100 + i)*100 + j)*100 + k
    int k = v % VGRID;
    int t = v / VGRID;
    int j = t % VGRID;
    int i = (t / VGRID) % VGRID;

    float* r = sh + threadIdx.x * COUT;
    r[0] = m0; r[1] = m1; r[2] = m2; r[3] = m3; r[4] = m4; r[5] = m5;
    r[6] = (float)i / 100.0f;
    r[7] = (float)j / 100.0f;
    r[8] = (float)k / 100.0f;
    r[9] = occ ? 1.0f : 0.0f;

    __syncthreads();

    // 2560 floats = 640 float4 per block, fully coalesced 16B stores
    float4* dst = reinterpret_cast<float4*>(out + (size_t)blockIdx.x * 256 * COUT);
    const float4* src = reinterpret_cast<const float4*>(sh);
    #pragma unroll
    for (int q = 0; q < 640; q += 256) {
        int idx = q + threadIdx.x;
        if (idx < 640) dst[idx] = src[idx];
    }
}

// ---------------------------------------------------------------------------
extern "C" void kernel_launch(void* const* d_in, const int* in_sizes, int n_in,
                              void* d_out, int out_size) {
    const float* coords = (const float*)d_in[0];
    const float* feats  = (const float*)d_in[1];
    float* out = (float*)d_out;

    scatter_kernel<<<NPOINTS / 256, 256>>>(coords, feats);
    finalize_kernel<<<NVOX / 256, 256>>>(out);
}